// round 10
// baseline (speedup 1.0000x reference)
#include <cuda_runtime.h>
#include <cuda_fp16.h>
#include <cstdint>

#define PP 32000
#define DD 128
#define BB 4096

// fp16 operands
__device__ __half g_hidden[BB * DD];   // [b][d]
__device__ __half g_Vt[PP * DD];       // [p][d]

__device__ __forceinline__ uint32_t smem_u32(const void* p) {
    uint32_t a;
    asm("{ .reg .u64 t; cvta.to.shared.u64 t, %1; cvt.u32.u64 %0, t; }" : "=r"(a) : "l"(p));
    return a;
}

// ------------------------------------------------- merged prologue kernel
#define HID_BLOCKS 4096
#define VC_BLOCKS  2048
__global__ void prologue_kernel(const int* __restrict__ x, const float* __restrict__ W,
                                const float* __restrict__ V, int M) {
    if (blockIdx.x < HID_BLOCKS) {
        int b = blockIdx.x;
        int d = threadIdx.x;
        const int* xb = x + b * M;
        float acc = 0.0f;
        for (int m = 0; m < M; ++m) acc += W[(size_t)d * PP + xb[m]];
        g_hidden[b * DD + d] = __float2half_rn(fmaxf(acc, 0.0f));
    } else {
        int i = (blockIdx.x - HID_BLOCKS) * blockDim.x + threadIdx.x;
        const float4* src = (const float4*)V;
        uint2* dst = (uint2*)g_Vt;
        const int n4 = PP * DD / 4;
        const int stride = VC_BLOCKS * blockDim.x;
        for (; i < n4; i += stride) {
            float4 v = src[i];
            __half2 lo = __floats2half2_rn(v.x, v.y);
            __half2 hi = __floats2half2_rn(v.z, v.w);
            dst[i] = make_uint2(*(uint32_t*)&lo, *(uint32_t*)&hi);
        }
    }
}

// --------------------------------------------------------------- GEMM kernel
// out[b][p] = sum_d hidden[b][d] * V[p][d], fp16 inputs, f32 accum.
// CTA tile 128(b) x 128(p), K = 128. 256 threads, 8 warps as 2(m) x 4(n),
// warp tile 64 x 32, mma.sync m16n8k16. 2 CTAs/SM -> 16 warps/SM (4/SMSP).
// A (128x128 f16, 32KB) loaded once per CTA; B tiles (32KB) double-buffered.
#define TMB 128
#define TN  128
#define NPT (PP / TN)   // 250
#define SPLIT 9
#define PCHUNK 28       // ceil(250/9)

#define SM_A  0
#define SM_B  32768             // 2 x 32768
#define SMEM_TOTAL 98304       // 96 KB -> 2 CTAs/SM

// tile: 128 rows x 256B (128 f16); 16B chunks, swizzle chunk ^= (row & 7)
__device__ __forceinline__ void load_tile_async(uint32_t dstBase, const __half* __restrict__ g,
                                                int tid) {
#pragma unroll
    for (int i = 0; i < 8; ++i) {
        int slot = tid + i * 256;      // 0..2047 16B chunks
        int row  = slot >> 4;          // 0..127
        int c    = slot & 15;
        uint32_t dst = dstBase + row * 256 + (((uint32_t)(c ^ (row & 7))) << 4);
        const __half* src = g + row * DD + c * 8;
        asm volatile("cp.async.cg.shared.global [%0], [%1], 16;" :: "r"(dst), "l"(src));
    }
}

__device__ __forceinline__ void ldsm_x4(uint32_t* r, uint32_t addr) {
    asm volatile("ldmatrix.sync.aligned.m8n8.x4.shared.b16 {%0,%1,%2,%3}, [%4];"
                 : "=r"(r[0]), "=r"(r[1]), "=r"(r[2]), "=r"(r[3]) : "r"(addr));
}

__device__ __forceinline__ void mma_f16(float* c, const uint32_t* a, const uint32_t* b) {
    asm volatile(
        "mma.sync.aligned.m16n8k16.row.col.f32.f16.f16.f32 "
        "{%0,%1,%2,%3}, {%4,%5,%6,%7}, {%8,%9}, {%0,%1,%2,%3};"
        : "+f"(c[0]), "+f"(c[1]), "+f"(c[2]), "+f"(c[3])
        : "r"(a[0]), "r"(a[1]), "r"(a[2]), "r"(a[3]), "r"(b[0]), "r"(b[1]));
}

__global__ __launch_bounds__(256, 2)
void gemm_mma(float* __restrict__ out) {
    extern __shared__ char smem[];
    uint32_t sb = smem_u32(smem);
    const int tid  = threadIdx.x;
    const int wid  = tid >> 5;
    const int lane = tid & 31;
    const int warpM = wid >> 2;       // 0..1  (64 rows each)
    const int warpN = wid & 3;        // 0..3  (32 cols each)
    const int g = lane >> 2;
    const int t = lane & 3;

    const int bTile = blockIdx.y;
    const int p0 = blockIdx.x * PCHUNK;
    const int p1 = min(NPT, p0 + PCHUNK);
    const int nT = p1 - p0;

    // A fragment addressing (m16k16 via ldsm.x4 on b16 8x8s)
    const int aRow  = warpM * 64 + (lane & 15);
    const int aHalf = lane >> 4;
    const uint32_t aBase = sb + SM_A + aRow * 256;   // + mi*4096 + swchunk<<4
    const int aR7 = aRow & 7;
    // B fragment addressing (n16k16 per ldsm.x4): covers 16 n-rows
    const int bRow  = warpN * 32 + ((lane >> 4) << 3) + (lane & 7);
    const int bHalf = (lane >> 3) & 1;
    const uint32_t bRowOff = (uint32_t)bRow * 256;   // + nj*4096 + swchunk<<4
    const int bR7 = bRow & 7;

    // ---- prologue: A (group 0) + first B tile (group 1) ----
    load_tile_async(sb + SM_A, g_hidden + (size_t)bTile * TMB * DD, tid);
    asm volatile("cp.async.commit_group;");
    load_tile_async(sb + SM_B, g_Vt + (size_t)p0 * TN * DD, tid);
    asm volatile("cp.async.commit_group;");

    float c[16][4];

    for (int it = 0; it < nT; ++it) {
        // prefetch next B into the other buffer
        if (it + 1 < nT) {
            load_tile_async(sb + SM_B + ((it + 1) & 1) * 32768,
                            g_Vt + (size_t)(p0 + it + 1) * TN * DD, tid);
            asm volatile("cp.async.commit_group;");
        }
        if (it + 1 < nT) asm volatile("cp.async.wait_group 1;" ::: "memory");
        else             asm volatile("cp.async.wait_group 0;" ::: "memory");
        __syncthreads();

        const uint32_t bbuf = sb + SM_B + (it & 1) * 32768;

#pragma unroll
        for (int i = 0; i < 16; ++i) { c[i][0] = 0.f; c[i][1] = 0.f; c[i][2] = 0.f; c[i][3] = 0.f; }

#pragma unroll
        for (int ks = 0; ks < 8; ++ks) {           // k16 steps
            const uint32_t axor = ((uint32_t)((ks * 2 + aHalf) ^ aR7)) << 4;
            const uint32_t bxor = ((uint32_t)((ks * 2 + bHalf) ^ bR7)) << 4;

            uint32_t a[4][4];
#pragma unroll
            for (int mi = 0; mi < 4; ++mi)
                ldsm_x4(a[mi], aBase + mi * 4096 + axor);

            uint32_t b[2][4];
#pragma unroll
            for (int nj = 0; nj < 2; ++nj)
                ldsm_x4(b[nj], bbuf + bRowOff + nj * 4096 + bxor);

            // b[nj]: {r0,r1} = first 8 n (k-lo/k-hi), {r2,r3} = second 8 n
#pragma unroll
            for (int mi = 0; mi < 4; ++mi)
#pragma unroll
                for (int ni = 0; ni < 4; ++ni)
                    mma_f16(c[mi * 4 + ni], a[mi], &b[ni >> 1][(ni & 1) * 2]);
        }

        // ---- epilogue: register -> gmem stores (float2) ----
        const size_t colBase = (size_t)(p0 + it) * TN + warpN * 32 + 2 * t;
#pragma unroll
        for (int mi = 0; mi < 4; ++mi) {
            const size_t row = (size_t)(bTile * TMB + warpM * 64 + mi * 16 + g);
#pragma unroll
            for (int ni = 0; ni < 4; ++ni) {
                const float* cc = c[mi * 4 + ni];
                size_t col = colBase + ni * 8;
                *(float2*)&out[row * PP + col]       = make_float2(cc[0], cc[1]);
                *(float2*)&out[(row + 8) * PP + col] = make_float2(cc[2], cc[3]);
            }
        }

        // protect the buffer the next iteration's prefetch will overwrite
        if (it + 1 < nT) __syncthreads();
    }
}

// ---------------------------------------------------------------------------
extern "C" void kernel_launch(void* const* d_in, const int* in_sizes, int n_in,
                              void* d_out, int out_size) {
    const int*   x  = (const int*)d_in[0];    // [B, M]
    const float* W  = (const float*)d_in[1];  // [D, P]
    const float* Vm = (const float*)d_in[2];  // [P, D]
    float* out = (float*)d_out;               // [B, P]

    int M = in_sizes[0] / BB;                 // = 2

    prologue_kernel<<<HID_BLOCKS + VC_BLOCKS, DD>>>(x, W, Vm, M);

    cudaFuncSetAttribute(gemm_mma, cudaFuncAttributeMaxDynamicSharedMemorySize, SMEM_TOTAL);
    dim3 grid(SPLIT, BB / TMB);               // (9, 32) = 288 blocks, 2 CTAs/SM
    gemm_mma<<<grid, 256, SMEM_TOTAL>>>(out);
}

// round 12
// speedup vs baseline: 1.1941x; 1.1941x over previous
#include <cuda_runtime.h>
#include <cuda_fp16.h>
#include <cstdint>

#define PP 32000
#define DD 128
#define BB 4096

// fp16 operands
__device__ __half g_hidden[BB * DD];   // [b][d]
__device__ __half g_Vt[PP * DD];       // [p][d]

__device__ __forceinline__ uint32_t smem_u32(const void* p) {
    uint32_t a;
    asm("{ .reg .u64 t; cvta.to.shared.u64 t, %1; cvt.u32.u64 %0, t; }" : "=r"(a) : "l"(p));
    return a;
}

// ------------------------------------------------- merged prologue kernel
#define HID_BLOCKS 4096
#define VC_BLOCKS  2048
__global__ void prologue_kernel(const int* __restrict__ x, const float* __restrict__ W,
                                const float* __restrict__ V, int M) {
    if (blockIdx.x < HID_BLOCKS) {
        int b = blockIdx.x;
        int d = threadIdx.x;
        const int* xb = x + b * M;
        float acc = 0.0f;
        for (int m = 0; m < M; ++m) acc += W[(size_t)d * PP + xb[m]];
        g_hidden[b * DD + d] = __float2half_rn(fmaxf(acc, 0.0f));
    } else {
        int i = (blockIdx.x - HID_BLOCKS) * blockDim.x + threadIdx.x;
        const float4* src = (const float4*)V;
        uint2* dst = (uint2*)g_Vt;
        const int n4 = PP * DD / 4;
        const int stride = VC_BLOCKS * blockDim.x;
        for (; i < n4; i += stride) {
            float4 v = src[i];
            __half2 lo = __floats2half2_rn(v.x, v.y);
            __half2 hi = __floats2half2_rn(v.z, v.w);
            dst[i] = make_uint2(*(uint32_t*)&lo, *(uint32_t*)&hi);
        }
    }
}

// --------------------------------------------------------------- GEMM kernel
// out[b][p] = sum_d hidden[b][d] * V[p][d], fp16 in, fp16 accum (split-K dual
// accumulators, f32 final sum). CTA tile 128x128, 128 threads, 4 warps 2(m)x2(n),
// warp tile 64x64, mma.sync m16n8k16. 2 CTAs/SM.
// A (32KB) loaded once per CTA; B tiles (32KB) double-buffered.
#define TMB 128
#define TN  128
#define NPT (PP / TN)   // 250
#define SPLIT 9
#define PCHUNK 28       // ceil(250/9)

#define SM_A  0
#define SM_B  32768             // 2 x 32768
#define SMEM_TOTAL 98304       // 96 KB -> 2 CTAs/SM

// tile: 128 rows x 256B (128 f16); 16B chunks, swizzle chunk ^= (row & 7)
__device__ __forceinline__ void load_tile_async(uint32_t dstBase, const __half* __restrict__ g,
                                                int tid) {
#pragma unroll
    for (int i = 0; i < 16; ++i) {
        int slot = tid + i * 128;      // 0..2047 16B chunks
        int row  = slot >> 4;          // 0..127
        int c    = slot & 15;
        uint32_t dst = dstBase + row * 256 + (((uint32_t)(c ^ (row & 7))) << 4);
        const __half* src = g + row * DD + c * 8;
        asm volatile("cp.async.cg.shared.global [%0], [%1], 16;" :: "r"(dst), "l"(src));
    }
}

__device__ __forceinline__ void ldsm_x4(uint32_t* r, uint32_t addr) {
    asm volatile("ldmatrix.sync.aligned.m8n8.x4.shared.b16 {%0,%1,%2,%3}, [%4];"
                 : "=r"(r[0]), "=r"(r[1]), "=r"(r[2]), "=r"(r[3]) : "r"(addr));
}

// fp16-accumulate mma: C/D are 2 regs of packed f16x2
__device__ __forceinline__ void mma_f16acc(uint32_t* c, const uint32_t* a, const uint32_t* b) {
    asm volatile(
        "mma.sync.aligned.m16n8k16.row.col.f16.f16.f16.f16 "
        "{%0,%1}, {%2,%3,%4,%5}, {%6,%7}, {%0,%1};"
        : "+r"(c[0]), "+r"(c[1])
        : "r"(a[0]), "r"(a[1]), "r"(a[2]), "r"(a[3]), "r"(b[0]), "r"(b[1]));
}

__global__ __launch_bounds__(128, 2)
void gemm_mma(float* __restrict__ out) {
    extern __shared__ char smem[];
    uint32_t sb = smem_u32(smem);
    const int tid  = threadIdx.x;
    const int wid  = tid >> 5;
    const int lane = tid & 31;
    const int warpM = wid >> 1;       // 0..1  (64 rows each)
    const int warpN = wid & 1;        // 0..1  (64 cols each)
    const int g = lane >> 2;
    const int t = lane & 3;

    const int bTile = blockIdx.y;
    const int p0 = blockIdx.x * PCHUNK;
    const int p1 = min(NPT, p0 + PCHUNK);
    const int nT = p1 - p0;

    // A fragment addressing (m16k16 via ldsm.x4 on b16 8x8s)
    const int aRow  = warpM * 64 + (lane & 15);
    const int aHalf = lane >> 4;
    const uint32_t aBase = sb + SM_A + aRow * 256;   // + mi*4096 + swchunk<<4
    const int aR7 = aRow & 7;
    // B fragment addressing (n16k16 per ldsm.x4)
    const int bRow  = warpN * 64 + ((lane >> 4) << 3) + (lane & 7);
    const int bHalf = (lane >> 3) & 1;
    const uint32_t bRowOff = (uint32_t)bRow * 256;   // + nj*4096 + swchunk<<4
    const int bR7 = bRow & 7;

    // ---- prologue: A (group 0) + first B tile (group 1) ----
    load_tile_async(sb + SM_A, g_hidden + (size_t)bTile * TMB * DD, tid);
    asm volatile("cp.async.commit_group;");
    load_tile_async(sb + SM_B, g_Vt + (size_t)p0 * TN * DD, tid);
    asm volatile("cp.async.commit_group;");

    // dual fp16 accumulator sets (split-K): [tile][set][2 regs]
    uint32_t c16[32][2][2];

    for (int it = 0; it < nT; ++it) {
        if (it + 1 < nT) {
            load_tile_async(sb + SM_B + ((it + 1) & 1) * 32768,
                            g_Vt + (size_t)(p0 + it + 1) * TN * DD, tid);
            asm volatile("cp.async.commit_group;");
        }
        if (it + 1 < nT) asm volatile("cp.async.wait_group 1;" ::: "memory");
        else             asm volatile("cp.async.wait_group 0;" ::: "memory");
        __syncthreads();

        const uint32_t bbuf = sb + SM_B + (it & 1) * 32768;

#pragma unroll
        for (int i = 0; i < 32; ++i) {
            c16[i][0][0] = 0u; c16[i][0][1] = 0u;
            c16[i][1][0] = 0u; c16[i][1][1] = 0u;
        }

#pragma unroll
        for (int ks = 0; ks < 8; ++ks) {           // k16 steps; set = ks>>2
            const uint32_t axor = ((uint32_t)((ks * 2 + aHalf) ^ aR7)) << 4;
            const uint32_t bxor = ((uint32_t)((ks * 2 + bHalf) ^ bR7)) << 4;
            const int set = ks >> 2;

            uint32_t a[4][4];
#pragma unroll
            for (int mi = 0; mi < 4; ++mi)
                ldsm_x4(a[mi], aBase + mi * 4096 + axor);

            uint32_t b[4][4];
#pragma unroll
            for (int nj = 0; nj < 4; ++nj)
                ldsm_x4(b[nj], bbuf + bRowOff + nj * 4096 + bxor);

#pragma unroll
            for (int mi = 0; mi < 4; ++mi)
#pragma unroll
                for (int ni = 0; ni < 8; ++ni)
                    mma_f16acc(c16[mi * 8 + ni][set], a[mi], &b[ni >> 1][(ni & 1) * 2]);
        }

        // ---- epilogue: combine sets in f32, store (float2) ----
        const size_t colBase = (size_t)(p0 + it) * TN + warpN * 64 + 2 * t;
#pragma unroll
        for (int mi = 0; mi < 4; ++mi) {
            const size_t row = (size_t)(bTile * TMB + warpM * 64 + mi * 16 + g);
#pragma unroll
            for (int ni = 0; ni < 8; ++ni) {
                const uint32_t* s0 = c16[mi * 8 + ni][0];
                const uint32_t* s1 = c16[mi * 8 + ni][1];
                float2 lo0 = __half22float2(*(const __half2*)&s0[0]);
                float2 lo1 = __half22float2(*(const __half2*)&s1[0]);
                float2 hi0 = __half22float2(*(const __half2*)&s0[1]);
                float2 hi1 = __half22float2(*(const __half2*)&s1[1]);
                size_t col = colBase + ni * 8;
                *(float2*)&out[row * PP + col] =
                    make_float2(lo0.x + lo1.x, lo0.y + lo1.y);
                *(float2*)&out[(row + 8) * PP + col] =
                    make_float2(hi0.x + hi1.x, hi0.y + hi1.y);
            }
        }

        if (it + 1 < nT) __syncthreads();
    }
}

// ---------------------------------------------------------------------------
extern "C" void kernel_launch(void* const* d_in, const int* in_sizes, int n_in,
                              void* d_out, int out_size) {
    const int*   x  = (const int*)d_in[0];    // [B, M]
    const float* W  = (const float*)d_in[1];  // [D, P]
    const float* Vm = (const float*)d_in[2];  // [P, D]
    float* out = (float*)d_out;               // [B, P]

    int M = in_sizes[0] / BB;                 // = 2

    prologue_kernel<<<HID_BLOCKS + VC_BLOCKS, DD>>>(x, W, Vm, M);

    cudaFuncSetAttribute(gemm_mma, cudaFuncAttributeMaxDynamicSharedMemorySize, SMEM_TOTAL);
    dim3 grid(SPLIT, BB / TMB);               // (9, 32) = 288 blocks, 2 CTAs/SM
    gemm_mma<<<grid, 128, SMEM_TOTAL>>>(out);
}